// round 14
// baseline (speedup 1.0000x reference)
#include <cuda_runtime.h>

#define FULLMASK 0xffffffffu
typedef unsigned long long ull;

namespace {
constexpr int BB = 256;
constexpr int TT = 2048;
constexpr int DD = 64;
constexpr int LBAND = 2;
constexpr int DB = 32;
constexpr int GG = 96;
constexpr int TPAD = TT + 64;  // dt rows padded so the 32-wide prefetch never reads OOB
}

// Scratch (module-static device globals; no runtime allocation)
__device__ float g_pdt[LBAND][BB][TPAD];
__device__ int   g_nv[LBAND][BB];
__device__ float g_c0[LBAND][BB][GG];
__device__ float g_c1[LBAND][BB][GG];
__device__ float g_h2[LBAND][BB][TT][DB];   // per-step layer-2 hidden states

// Named-barrier producer/consumer primitives (count = 64: 32 arrive + 32 sync)
#define NBAR_SYNC(id)   asm volatile("bar.sync %0, 64;"   :: "r"(id) : "memory")
#define NBAR_ARRIVE(id) asm volatile("bar.arrive %0, 64;" :: "r"(id) : "memory")

// ---------------------------------------------------------------------------
// Kernel 1: stable compaction of valid dtime values per (band,row) + counts
// ---------------------------------------------------------------------------
__global__ void compact_kernel(const int* __restrict__ band_ids,
                               const float* __restrict__ dtime) {
    int warp = threadIdx.x >> 5;
    int lane = threadIdx.x & 31;
    int b = blockIdx.x * (blockDim.x >> 5) + warp;
    if (b >= BB) return;
    int cnt0 = 0, cnt1 = 0;
    int   idc = band_ids[b * TT + lane];
    float dtc = dtime[b * TT + lane];
    for (int base = 0; base < TT; base += 32) {
        int idn = 0; float dtn = 0.f;
        if (base + 32 < TT) {                       // prefetch next tile
            idn = band_ids[b * TT + base + 32 + lane];
            dtn = dtime[b * TT + base + 32 + lane];
        }
        unsigned m0 = __ballot_sync(FULLMASK, idc == 0);
        unsigned lt = (1u << lane) - 1u;
        if (idc == 0) {
            g_pdt[0][b][cnt0 + __popc(m0 & lt)] = dtc;
        } else {
            g_pdt[1][b][cnt1 + __popc((~m0) & lt)] = dtc;
        }
        int p0 = __popc(m0);
        cnt0 += p0;
        cnt1 += 32 - p0;
        idc = idn; dtc = dtn;
    }
    if (lane == 0) { g_nv[0][b] = cnt0; g_nv[1][b] = cnt1; }
}

// ---------------------------------------------------------------------------
// Kernel 2: per-(band,row) affine layer-1 gate constants (bhh folded for r,z)
// ---------------------------------------------------------------------------
__global__ void rowconst_kernel(const float* __restrict__ z_last,
                                const float* __restrict__ proj_W,
                                const float* __restrict__ proj_b,
                                const float* __restrict__ Wih,
                                const float* __restrict__ bih,
                                const float* __restrict__ bhh) {
    int warp = threadIdx.x >> 5;
    int lane = threadIdx.x & 31;
    int wg = blockIdx.x * (blockDim.x >> 5) + warp;
    if (wg >= LBAND * BB) return;
    int kb = wg >> 8;
    int b  = wg & 255;

    float base = proj_b[kb * DB + lane];
#pragma unroll 8
    for (int i = 0; i < DD; i++) {
        base = fmaf(z_last[b * DD + i],
                    proj_W[(kb * (DD + 1) + i) * DB + lane], base);
    }
    float w65 = proj_W[(kb * (DD + 1) + DD) * DB + lane];

    for (int gi = 0; gi < 3; gi++) {
        int g = lane + 32 * gi;
        float c0a = bih[(kb * 2 + 0) * GG + g];
        if (gi < 2) c0a += bhh[(kb * 2 + 0) * GG + g];
        float c1a = 0.f;
        for (int j = 0; j < DB; j++) {
            float bj = __shfl_sync(FULLMASK, base, j);
            float wj = __shfl_sync(FULLMASK, w65, j);
            float w  = Wih[((kb * 2 + 0) * GG + g) * DB + j];
            c0a = fmaf(w, bj, c0a);
            c1a = fmaf(w, wj, c1a);
        }
        g_c0[kb][b][g] = c0a;
        g_c1[kb][b][g] = c1a;
    }
}

// ---------------------------------------------------------------------------
// helpers
// ---------------------------------------------------------------------------
__device__ __forceinline__ ull ffma2(ull a, ull b, ull c) {
    ull d;
    asm("fma.rn.f32x2 %0, %1, %2, %3;" : "=l"(d) : "l"(a), "l"(b), "l"(c));
    return d;
}
__device__ __forceinline__ float hsum2(ull p) {
    float lo, hi;
    asm("mov.b64 {%0, %1}, %2;" : "=f"(lo), "=f"(hi) : "l"(p));
    return lo + hi;
}
__device__ __forceinline__ float hsum4(ull a, ull b) {
    ull s;
    asm("add.rn.f32x2 %0, %1, %2;" : "=l"(s) : "l"(a), "l"(b));
    return hsum2(s);
}
__device__ __forceinline__ ull pack2(float a, float b) {
    ull p;
    asm("mov.b64 %0, {%1, %2};" : "=l"(p) : "f"(a), "f"(b));
    return p;
}
__device__ __forceinline__ float fast_sigmoid(float x) {
    return __fdividef(1.0f, 1.0f + __expf(-x));
}
__device__ __forceinline__ float fast_tanh(float x) {
    return __fdividef(2.0f, 1.0f + __expf(-2.0f * x)) - 1.0f;
}

// ---------------------------------------------------------------------------
// Main GRU kernel: 1 block (4 warps) per TWO sequences, decoupled A/B pairs.
//   wid 0: A(seq0)   wid 1: B(seq0)   wid 2: A(seq1)   wid 3: B(seq1)
// All four SMSPs carry work. Per sequence: warp A runs layer-1 + the r/z
// input gates of layer 2; warp B runs layer-2 and writes h2 to gmem.
// Handoff via 4-deep smem rings + parity-paired named barriers (full:
// base+0/1, empty: base+2/3; count 64; slack 2). This configuration measured
// 436.0 us and sits at ~87% of the fp32 FMA-pipe roofline on the pacing SMs
// (144 FFMA2 per SMSP-step); later "balancing" variants regressed, so this
// is the final banked version.
// ---------------------------------------------------------------------------
__global__ __launch_bounds__(128, 1)
void gru_main_kernel(const float* __restrict__ Wih,
                     const float* __restrict__ Whh,
                     const float* __restrict__ bih,
                     const float* __restrict__ bhh) {
    __shared__ __align__(8) float h1ring[2][4][DB];
    __shared__ __align__(8) float grbuf[2][4][DB];
    __shared__ __align__(8) float gzbuf[2][4][DB];
    __shared__ __align__(8) float h2ring[2][2][DB];

    const int wid  = threadIdx.x >> 5;
    const int lane = threadIdx.x & 31;
    const int seq  = wid >> 1;            // 0 or 1
    const int row  = blockIdx.x * 2 + seq;   // kb*256 + b
    const int kb   = row >> 8;
    const int b    = row & 255;
    const int fullb  = 1 + seq * 4;       // full barriers: fullb, fullb+1
    const int emptyb = fullb + 2;         // empty barriers: emptyb, emptyb+1

    const int nv = g_nv[kb][b];
    const float* __restrict__ pdt = &g_pdt[kb][b][0];
    float* __restrict__ h2row = &g_h2[kb][b][0][0];

    if ((wid & 1) == 0) {
        // ===== Warp A: layer 1 + r/z input gates of layer 2 =====
        ull w1r[16], w1z[16], w1n[16], wir[16], wiz[16];
        {
            const ull* pr = (const ull*)(Whh + ((size_t)((kb * 2 + 0) * GG + lane)      * DB));
            const ull* pz = (const ull*)(Whh + ((size_t)((kb * 2 + 0) * GG + lane + 32) * DB));
            const ull* pn = (const ull*)(Whh + ((size_t)((kb * 2 + 0) * GG + lane + 64) * DB));
            const ull* qr = (const ull*)(Wih + ((size_t)((kb * 2 + 1) * GG + lane)      * DB));
            const ull* qz = (const ull*)(Wih + ((size_t)((kb * 2 + 1) * GG + lane + 32) * DB));
#pragma unroll
            for (int k = 0; k < 16; k++) {
                w1r[k] = pr[k]; w1z[k] = pz[k]; w1n[k] = pn[k];
                wir[k] = qr[k]; wiz[k] = qz[k];
            }
        }
        const float c0r = g_c0[kb][b][lane];
        const float c0z = g_c0[kb][b][lane + 32];
        const float c0n = g_c0[kb][b][lane + 64];
        const float c1r = g_c1[kb][b][lane];
        const float c1z = g_c1[kb][b][lane + 32];
        const float c1n = g_c1[kb][b][lane + 64];
        const float bh1n = bhh[(kb * 2 + 0) * GG + lane + 64];

        // prologue: h1(0) from dt(0) with h=0 (recurrent terms vanish except bh1n)
        float dtv = pdt[lane];
        float dt0 = __shfl_sync(FULLMASK, dtv, 0);
        float r1 = fast_sigmoid(fmaf(dt0, c1r, c0r));
        float z1 = fast_sigmoid(fmaf(dt0, c1z, c0z));
        float n1 = fast_tanh(fmaf(dt0, c1n, c0n) + r1 * bh1n);
        float h1 = (1.f - z1) * n1;
        h1ring[seq][0][lane] = h1;
        __syncwarp();

        for (int i = 0; i < nv; i++) {
            if (i >= 2) NBAR_SYNC(emptyb + (i & 1));   // slot freed by B's j = i-2
            if (((i + 1) & 31) == 0) dtv = pdt[i + 1 + lane];   // TPAD: never OOB
            float dtn = __shfl_sync(FULLMASK, dtv, (i + 1) & 31);

            const ull* hp = (const ull*)h1ring[seq][i & 3];     // h1(i), own data
            ull aR0 = 0, aR1 = 0, aZ0 = 0, aZ1 = 0, aN0 = 0, aN1 = 0;
            ull gR0 = 0, gR1 = 0, gZ0 = 0, gZ1 = 0;
#pragma unroll
            for (int k = 0; k < 8; k++) {                       // dual trees, depth 8
                ull p0 = hp[2 * k], p1 = hp[2 * k + 1];
                aR0 = ffma2(w1r[2 * k], p0, aR0); aR1 = ffma2(w1r[2 * k + 1], p1, aR1);
                aZ0 = ffma2(w1z[2 * k], p0, aZ0); aZ1 = ffma2(w1z[2 * k + 1], p1, aZ1);
                aN0 = ffma2(w1n[2 * k], p0, aN0); aN1 = ffma2(w1n[2 * k + 1], p1, aN1);
                gR0 = ffma2(wir[2 * k], p0, gR0); gR1 = ffma2(wir[2 * k + 1], p1, gR1);
                gZ0 = ffma2(wiz[2 * k], p0, gZ0); gZ1 = ffma2(wiz[2 * k + 1], p1, gZ1);
            }
            grbuf[seq][i & 3][lane] = hsum4(gR0, gR1);          // gr(i)
            gzbuf[seq][i & 3][lane] = hsum4(gZ0, gZ1);          // gz(i)

            r1 = fast_sigmoid(fmaf(dtn, c1r, c0r) + hsum4(aR0, aR1));
            z1 = fast_sigmoid(fmaf(dtn, c1z, c0z) + hsum4(aZ0, aZ1));
            n1 = fast_tanh(fmaf(dtn, c1n, c0n) + r1 * (hsum4(aN0, aN1) + bh1n));
            h1 = fmaf(z1, h1 - n1, n1);                         // h1(i+1)
            h1ring[seq][(i + 1) & 3][lane] = h1;
            __syncwarp();                                       // own cross-lane reads
            NBAR_ARRIVE(fullb + (i & 1));                       // publish step i
        }
    } else {
        // ===== Warp B: layer 2 recurrence =====
        ull w2r[16], w2z[16], w2n[16], win[16];
        {
            const ull* pr = (const ull*)(Whh + ((size_t)((kb * 2 + 1) * GG + lane)      * DB));
            const ull* pz = (const ull*)(Whh + ((size_t)((kb * 2 + 1) * GG + lane + 32) * DB));
            const ull* pn = (const ull*)(Whh + ((size_t)((kb * 2 + 1) * GG + lane + 64) * DB));
            const ull* qn = (const ull*)(Wih + ((size_t)((kb * 2 + 1) * GG + lane + 64) * DB));
#pragma unroll
            for (int k = 0; k < 16; k++) {
                w2r[k] = pr[k]; w2z[k] = pz[k]; w2n[k] = pn[k]; win[k] = qn[k];
            }
        }
        const float b2r  = bih[(kb * 2 + 1) * GG + lane]      + bhh[(kb * 2 + 1) * GG + lane];
        const float b2z  = bih[(kb * 2 + 1) * GG + lane + 32] + bhh[(kb * 2 + 1) * GG + lane + 32];
        const float bi2n = bih[(kb * 2 + 1) * GG + lane + 64];
        const float bh2n = bhh[(kb * 2 + 1) * GG + lane + 64];

        h2ring[seq][0][lane] = 0.f;
        h2ring[seq][1][lane] = 0.f;
        float h2 = 0.f;
        __syncwarp();

        for (int j = 0; j < nv; j++) {
            NBAR_SYNC(fullb + (j & 1));             // wait A's publish of step j
            const ull* hpj = (const ull*)h1ring[seq][j & 3];         // h1(j)
            const ull* hp2 = (const ull*)h2ring[seq][(j + 1) & 1];   // h2(j-1)
            ull r0 = 0, r1_ = 0, z0 = 0, z1_ = 0, n0 = 0, n1_ = 0, in0 = 0, in1 = 0;
#pragma unroll
            for (int k = 0; k < 8; k++) {
                ull p0 = hpj[2 * k], p1 = hpj[2 * k + 1];
                ull q0 = hp2[2 * k], q1 = hp2[2 * k + 1];
                r0 = ffma2(w2r[2 * k], q0, r0); r1_ = ffma2(w2r[2 * k + 1], q1, r1_);
                z0 = ffma2(w2z[2 * k], q0, z0); z1_ = ffma2(w2z[2 * k + 1], q1, z1_);
                n0 = ffma2(w2n[2 * k], q0, n0); n1_ = ffma2(w2n[2 * k + 1], q1, n1_);
                in0 = ffma2(win[2 * k], p0, in0); in1 = ffma2(win[2 * k + 1], p1, in1);
            }
            float r2 = fast_sigmoid(grbuf[seq][j & 3][lane] + hsum4(r0, r1_) + b2r);
            float z2 = fast_sigmoid(gzbuf[seq][j & 3][lane] + hsum4(z0, z1_) + b2z);
            float n2 = fast_tanh(hsum4(in0, in1) + bi2n + r2 * (hsum4(n0, n1_) + bh2n));
            h2 = fmaf(z2, h2 - n2, n2);                          // h2(j)
            h2ring[seq][j & 1][lane] = h2;
            __syncwarp();                                        // own cross-lane reads
            NBAR_ARRIVE(emptyb + (j & 1));                       // free slot j
            h2row[(size_t)j * DB + lane] = h2;                   // coalesced STG
        }
    }
}

// ---------------------------------------------------------------------------
// Pass 2: massively parallel output MLP with tail skip.
// ---------------------------------------------------------------------------
__global__ __launch_bounds__(128)
void mlp_kernel(const float* __restrict__ mW1,
                const float* __restrict__ mb1,
                const float* __restrict__ mW2,
                const float* __restrict__ mb2,
                float* __restrict__ out) {
    __shared__ __align__(8) ull   sM1p[DB / 2][DB];   // (mW1[2k][l], mW1[2k+1][l])
    __shared__ __align__(8) float sh[4][32][34];      // per-warp h2 tile, padded
    __shared__ float smb1[DB], smw2[DB];

    const int row = blockIdx.x >> 4;     // 0..511 = kb*256 + b
    const int tg  = blockIdx.x & 15;
    const int kb  = row >> 8;
    const int b   = row & 255;
    const int wid  = threadIdx.x >> 5;
    const int lane = threadIdx.x & 31;

    for (int idx = threadIdx.x; idx < (DB / 2) * DB; idx += blockDim.x) {
        int k = idx >> 5, l = idx & 31;
        sM1p[k][l] = pack2(mW1[kb * DB * DB + (2 * k) * DB + l],
                           mW1[kb * DB * DB + (2 * k + 1) * DB + l]);
    }
    if (threadIdx.x < DB) {
        smb1[threadIdx.x] = mb1[kb * DB + threadIdx.x];
        smw2[threadIdx.x] = mW2[kb * DB + threadIdx.x];
    }
    __syncthreads();

    const int nv   = g_nv[kb][b];
    const int tile = tg * 4 + wid;       // 0..63
    const int t0   = tile * 32;
    const bool boundary = (tile == (nv >> 5));
    if (t0 >= nv && !boundary) return;   // pure-tail tile: filled by boundary warp

    const float* __restrict__ hbase = &g_h2[kb][b][0][0];

    for (int j = 0; j < 32; j++) {
        int t = t0 + j;
        int src = (t < nv) ? t : (nv - 1);
        float v = (nv > 0) ? hbase[(size_t)src * DB + lane] : 0.f;
        sh[wid][j][lane] = v;
    }
    __syncwarp();

    const ull* hrow = (const ull*)&sh[wid][lane][0];
    ull hr[16];
#pragma unroll
    for (int k = 0; k < 16; k++) hr[k] = hrow[k];

    float y = mb2[kb];
#pragma unroll 8
    for (int l = 0; l < DB; l++) {
        ull acc = 0ull;
#pragma unroll
        for (int k = 0; k < 16; k++)
            acc = ffma2(sM1p[k][l], hr[k], acc);
        float hid = fmaxf(hsum2(acc) + smb1[l], 0.f);
        y = fmaf(hid, smw2[l], y);
    }

    float* __restrict__ orow = out + (size_t)row * TT;
    if (!boundary) {
        orow[t0 + lane] = y;
    } else {
        if (t0 + lane < nv) orow[t0 + lane] = y;
        int idx = nv - 1 - t0;
        idx = idx < 0 ? 0 : (idx > 31 ? 31 : idx);
        float y_last = __shfl_sync(FULLMASK, y, idx);
        for (int t = nv + lane; t < TT; t += 32) orow[t] = y_last;
    }
}

// ---------------------------------------------------------------------------
extern "C" void kernel_launch(void* const* d_in, const int* in_sizes, int n_in,
                              void* d_out, int out_size) {
    const int*   band_ids = (const int*)  d_in[0];
    const float* dtime    = (const float*)d_in[1];
    const float* z_last   = (const float*)d_in[2];
    const float* proj_W   = (const float*)d_in[3];
    const float* proj_b   = (const float*)d_in[4];
    const float* Wih      = (const float*)d_in[5];
    const float* Whh      = (const float*)d_in[6];
    const float* bih      = (const float*)d_in[7];
    const float* bhh      = (const float*)d_in[8];
    const float* mW1      = (const float*)d_in[9];
    const float* mb1      = (const float*)d_in[10];
    const float* mW2      = (const float*)d_in[11];
    const float* mb2      = (const float*)d_in[12];
    float* out = (float*)d_out;

    compact_kernel<<<BB / 8, 256>>>(band_ids, dtime);
    rowconst_kernel<<<(LBAND * BB) / 4, 128>>>(z_last, proj_W, proj_b, Wih, bih, bhh);
    gru_main_kernel<<<LBAND * BB / 2, 128>>>(Wih, Whh, bih, bhh);
    mlp_kernel<<<LBAND * BB * 16, 128>>>(mW1, mb1, mW2, mb2, out);
}

// round 15
// speedup vs baseline: 1.0036x; 1.0036x over previous
#include <cuda_runtime.h>

#define FULLMASK 0xffffffffu
typedef unsigned long long ull;

namespace {
constexpr int BB = 256;
constexpr int TT = 2048;
constexpr int DD = 64;
constexpr int LBAND = 2;
constexpr int DB = 32;
constexpr int GG = 96;
constexpr int TPAD = TT + 64;  // dt rows padded so the 32-wide prefetch never reads OOB
}

// Scratch (module-static device globals; no runtime allocation)
__device__ float g_pdt[LBAND][BB][TPAD];
__device__ int   g_nv[LBAND][BB];
__device__ float g_c0[LBAND][BB][GG];
__device__ float g_c1[LBAND][BB][GG];
__device__ float g_h2[LBAND][BB][TT][DB];   // per-step layer-2 hidden states

// Named-barrier producer/consumer primitives (count = 64: 32 arrive + 32 sync)
#define NBAR_SYNC(id)   asm volatile("bar.sync %0, 64;"   :: "r"(id) : "memory")
#define NBAR_ARRIVE(id) asm volatile("bar.arrive %0, 64;" :: "r"(id) : "memory")

// ---------------------------------------------------------------------------
// Kernel 1: stable compaction of valid dtime values per (band,row) + counts
// ---------------------------------------------------------------------------
__global__ void compact_kernel(const int* __restrict__ band_ids,
                               const float* __restrict__ dtime) {
    int warp = threadIdx.x >> 5;
    int lane = threadIdx.x & 31;
    int b = blockIdx.x * (blockDim.x >> 5) + warp;
    if (b >= BB) return;
    int cnt0 = 0, cnt1 = 0;
    int   idc = band_ids[b * TT + lane];
    float dtc = dtime[b * TT + lane];
    for (int base = 0; base < TT; base += 32) {
        int idn = 0; float dtn = 0.f;
        if (base + 32 < TT) {                       // prefetch next tile
            idn = band_ids[b * TT + base + 32 + lane];
            dtn = dtime[b * TT + base + 32 + lane];
        }
        unsigned m0 = __ballot_sync(FULLMASK, idc == 0);
        unsigned lt = (1u << lane) - 1u;
        if (idc == 0) {
            g_pdt[0][b][cnt0 + __popc(m0 & lt)] = dtc;
        } else {
            g_pdt[1][b][cnt1 + __popc((~m0) & lt)] = dtc;
        }
        int p0 = __popc(m0);
        cnt0 += p0;
        cnt1 += 32 - p0;
        idc = idn; dtc = dtn;
    }
    if (lane == 0) { g_nv[0][b] = cnt0; g_nv[1][b] = cnt1; }
}

// ---------------------------------------------------------------------------
// Kernel 2: per-(band,row) affine layer-1 gate constants (bhh folded for r,z)
// ---------------------------------------------------------------------------
__global__ void rowconst_kernel(const float* __restrict__ z_last,
                                const float* __restrict__ proj_W,
                                const float* __restrict__ proj_b,
                                const float* __restrict__ Wih,
                                const float* __restrict__ bih,
                                const float* __restrict__ bhh) {
    int warp = threadIdx.x >> 5;
    int lane = threadIdx.x & 31;
    int wg = blockIdx.x * (blockDim.x >> 5) + warp;
    if (wg >= LBAND * BB) return;
    int kb = wg >> 8;
    int b  = wg & 255;

    float base = proj_b[kb * DB + lane];
#pragma unroll 8
    for (int i = 0; i < DD; i++) {
        base = fmaf(z_last[b * DD + i],
                    proj_W[(kb * (DD + 1) + i) * DB + lane], base);
    }
    float w65 = proj_W[(kb * (DD + 1) + DD) * DB + lane];

    for (int gi = 0; gi < 3; gi++) {
        int g = lane + 32 * gi;
        float c0a = bih[(kb * 2 + 0) * GG + g];
        if (gi < 2) c0a += bhh[(kb * 2 + 0) * GG + g];
        float c1a = 0.f;
        for (int j = 0; j < DB; j++) {
            float bj = __shfl_sync(FULLMASK, base, j);
            float wj = __shfl_sync(FULLMASK, w65, j);
            float w  = Wih[((kb * 2 + 0) * GG + g) * DB + j];
            c0a = fmaf(w, bj, c0a);
            c1a = fmaf(w, wj, c1a);
        }
        g_c0[kb][b][g] = c0a;
        g_c1[kb][b][g] = c1a;
    }
}

// ---------------------------------------------------------------------------
// helpers
// ---------------------------------------------------------------------------
__device__ __forceinline__ ull ffma2(ull a, ull b, ull c) {
    ull d;
    asm("fma.rn.f32x2 %0, %1, %2, %3;" : "=l"(d) : "l"(a), "l"(b), "l"(c));
    return d;
}
__device__ __forceinline__ float hsum2(ull p) {
    float lo, hi;
    asm("mov.b64 {%0, %1}, %2;" : "=f"(lo), "=f"(hi) : "l"(p));
    return lo + hi;
}
__device__ __forceinline__ float hsum4(ull a, ull b) {
    ull s;
    asm("add.rn.f32x2 %0, %1, %2;" : "=l"(s) : "l"(a), "l"(b));
    return hsum2(s);
}
__device__ __forceinline__ ull pack2(float a, float b) {
    ull p;
    asm("mov.b64 %0, {%1, %2};" : "=l"(p) : "f"(a), "f"(b));
    return p;
}
__device__ __forceinline__ float fast_sigmoid(float x) {
    return __fdividef(1.0f, 1.0f + __expf(-x));
}
__device__ __forceinline__ float fast_tanh(float x) {
    return __fdividef(2.0f, 1.0f + __expf(-2.0f * x)) - 1.0f;
}

// Per-block phase skew: a dependent chain of exact identity FMAs (x = x*1+0)
// that delays this warp's loop start by ~4*n cycles without changing values.
// Decorrelates co-resident blocks' compute phases so same-role warps sharing
// an SMSP don't hit their FMA bursts / serial gate phases in lockstep.
__device__ __forceinline__ float phase_skew(float x, int n) {
    for (int k = 0; k < n; k++)
        asm volatile("fma.rn.f32 %0, %0, 0f3F800000, 0f00000000;" : "+f"(x));
    return x;
}

// ---------------------------------------------------------------------------
// Main GRU kernel: 1 block (4 warps) per TWO sequences, decoupled A/B pairs.
//   wid 0: A(seq0)   wid 1: B(seq0)   wid 2: A(seq1)   wid 3: B(seq1)
// Per sequence: warp A runs layer-1 + the r/z input gates of layer 2; warp B
// runs layer-2 and writes h2 to gmem. Handoff via 4-deep smem rings +
// parity-paired named barriers (full: base+0/1, empty: base+2/3; count 64;
// slack 2). Identical to the 436us R9 kernel except for the per-block
// phase_skew at loop entry.
// ---------------------------------------------------------------------------
__global__ __launch_bounds__(128, 1)
void gru_main_kernel(const float* __restrict__ Wih,
                     const float* __restrict__ Whh,
                     const float* __restrict__ bih,
                     const float* __restrict__ bhh) {
    __shared__ __align__(8) float h1ring[2][4][DB];
    __shared__ __align__(8) float grbuf[2][4][DB];
    __shared__ __align__(8) float gzbuf[2][4][DB];
    __shared__ __align__(8) float h2ring[2][2][DB];

    const int wid  = threadIdx.x >> 5;
    const int lane = threadIdx.x & 31;
    const int seq  = wid >> 1;            // 0 or 1
    const int row  = blockIdx.x * 2 + seq;   // kb*256 + b
    const int kb   = row >> 8;
    const int b    = row & 255;
    const int fullb  = 1 + seq * 4;       // full barriers: fullb, fullb+1
    const int emptyb = fullb + 2;         // empty barriers: emptyb, emptyb+1
    const int skew = (blockIdx.x * 37) & 63;   // per-block, 0..63 (~0-250 cyc)

    const int nv = g_nv[kb][b];
    const float* __restrict__ pdt = &g_pdt[kb][b][0];
    float* __restrict__ h2row = &g_h2[kb][b][0][0];

    if ((wid & 1) == 0) {
        // ===== Warp A: layer 1 + r/z input gates of layer 2 =====
        ull w1r[16], w1z[16], w1n[16], wir[16], wiz[16];
        {
            const ull* pr = (const ull*)(Whh + ((size_t)((kb * 2 + 0) * GG + lane)      * DB));
            const ull* pz = (const ull*)(Whh + ((size_t)((kb * 2 + 0) * GG + lane + 32) * DB));
            const ull* pn = (const ull*)(Whh + ((size_t)((kb * 2 + 0) * GG + lane + 64) * DB));
            const ull* qr = (const ull*)(Wih + ((size_t)((kb * 2 + 1) * GG + lane)      * DB));
            const ull* qz = (const ull*)(Wih + ((size_t)((kb * 2 + 1) * GG + lane + 32) * DB));
#pragma unroll
            for (int k = 0; k < 16; k++) {
                w1r[k] = pr[k]; w1z[k] = pz[k]; w1n[k] = pn[k];
                wir[k] = qr[k]; wiz[k] = qz[k];
            }
        }
        const float c0r = g_c0[kb][b][lane];
        const float c0z = g_c0[kb][b][lane + 32];
        const float c0n = g_c0[kb][b][lane + 64];
        const float c1r = g_c1[kb][b][lane];
        const float c1z = g_c1[kb][b][lane + 32];
        const float c1n = g_c1[kb][b][lane + 64];
        const float bh1n = bhh[(kb * 2 + 0) * GG + lane + 64];

        // prologue: h1(0) from dt(0) with h=0 (recurrent terms vanish except bh1n)
        float dtv = pdt[lane];
        dtv = phase_skew(dtv, skew);               // exact identity, breaks lockstep
        float dt0 = __shfl_sync(FULLMASK, dtv, 0);
        float r1 = fast_sigmoid(fmaf(dt0, c1r, c0r));
        float z1 = fast_sigmoid(fmaf(dt0, c1z, c0z));
        float n1 = fast_tanh(fmaf(dt0, c1n, c0n) + r1 * bh1n);
        float h1 = (1.f - z1) * n1;
        h1ring[seq][0][lane] = h1;
        __syncwarp();

        for (int i = 0; i < nv; i++) {
            if (i >= 2) NBAR_SYNC(emptyb + (i & 1));   // slot freed by B's j = i-2
            if (((i + 1) & 31) == 0) dtv = pdt[i + 1 + lane];   // TPAD: never OOB
            float dtn = __shfl_sync(FULLMASK, dtv, (i + 1) & 31);

            const ull* hp = (const ull*)h1ring[seq][i & 3];     // h1(i), own data
            ull aR0 = 0, aR1 = 0, aZ0 = 0, aZ1 = 0, aN0 = 0, aN1 = 0;
            ull gR0 = 0, gR1 = 0, gZ0 = 0, gZ1 = 0;
#pragma unroll
            for (int k = 0; k < 8; k++) {                       // dual trees, depth 8
                ull p0 = hp[2 * k], p1 = hp[2 * k + 1];
                aR0 = ffma2(w1r[2 * k], p0, aR0); aR1 = ffma2(w1r[2 * k + 1], p1, aR1);
                aZ0 = ffma2(w1z[2 * k], p0, aZ0); aZ1 = ffma2(w1z[2 * k + 1], p1, aZ1);
                aN0 = ffma2(w1n[2 * k], p0, aN0); aN1 = ffma2(w1n[2 * k + 1], p1, aN1);
                gR0 = ffma2(wir[2 * k], p0, gR0); gR1 = ffma2(wir[2 * k + 1], p1, gR1);
                gZ0 = ffma2(wiz[2 * k], p0, gZ0); gZ1 = ffma2(wiz[2 * k + 1], p1, gZ1);
            }
            grbuf[seq][i & 3][lane] = hsum4(gR0, gR1);          // gr(i)
            gzbuf[seq][i & 3][lane] = hsum4(gZ0, gZ1);          // gz(i)

            r1 = fast_sigmoid(fmaf(dtn, c1r, c0r) + hsum4(aR0, aR1));
            z1 = fast_sigmoid(fmaf(dtn, c1z, c0z) + hsum4(aZ0, aZ1));
            n1 = fast_tanh(fmaf(dtn, c1n, c0n) + r1 * (hsum4(aN0, aN1) + bh1n));
            h1 = fmaf(z1, h1 - n1, n1);                         // h1(i+1)
            h1ring[seq][(i + 1) & 3][lane] = h1;
            __syncwarp();                                       // own cross-lane reads
            NBAR_ARRIVE(fullb + (i & 1));                       // publish step i
        }
    } else {
        // ===== Warp B: layer 2 recurrence =====
        ull w2r[16], w2z[16], w2n[16], win[16];
        {
            const ull* pr = (const ull*)(Whh + ((size_t)((kb * 2 + 1) * GG + lane)      * DB));
            const ull* pz = (const ull*)(Whh + ((size_t)((kb * 2 + 1) * GG + lane + 32) * DB));
            const ull* pn = (const ull*)(Whh + ((size_t)((kb * 2 + 1) * GG + lane + 64) * DB));
            const ull* qn = (const ull*)(Wih + ((size_t)((kb * 2 + 1) * GG + lane + 64) * DB));
#pragma unroll
            for (int k = 0; k < 16; k++) {
                w2r[k] = pr[k]; w2z[k] = pz[k]; w2n[k] = pn[k]; win[k] = qn[k];
            }
        }
        const float b2r  = bih[(kb * 2 + 1) * GG + lane]      + bhh[(kb * 2 + 1) * GG + lane];
        const float b2z  = bih[(kb * 2 + 1) * GG + lane + 32] + bhh[(kb * 2 + 1) * GG + lane + 32];
        const float bi2n = bih[(kb * 2 + 1) * GG + lane + 64];
        const float bh2n = bhh[(kb * 2 + 1) * GG + lane + 64];

        h2ring[seq][0][lane] = 0.f;
        h2ring[seq][1][lane] = 0.f;
        float h2 = 0.f;
        h2 = phase_skew(h2, skew);                 // exact identity (0*1+0 = 0)
        __syncwarp();

        for (int j = 0; j < nv; j++) {
            NBAR_SYNC(fullb + (j & 1));             // wait A's publish of step j
            const ull* hpj = (const ull*)h1ring[seq][j & 3];         // h1(j)
            const ull* hp2 = (const ull*)h2ring[seq][(j + 1) & 1];   // h2(j-1)
            ull r0 = 0, r1_ = 0, z0 = 0, z1_ = 0, n0 = 0, n1_ = 0, in0 = 0, in1 = 0;
#pragma unroll
            for (int k = 0; k < 8; k++) {
                ull p0 = hpj[2 * k], p1 = hpj[2 * k + 1];
                ull q0 = hp2[2 * k], q1 = hp2[2 * k + 1];
                r0 = ffma2(w2r[2 * k], q0, r0); r1_ = ffma2(w2r[2 * k + 1], q1, r1_);
                z0 = ffma2(w2z[2 * k], q0, z0); z1_ = ffma2(w2z[2 * k + 1], q1, z1_);
                n0 = ffma2(w2n[2 * k], q0, n0); n1_ = ffma2(w2n[2 * k + 1], q1, n1_);
                in0 = ffma2(win[2 * k], p0, in0); in1 = ffma2(win[2 * k + 1], p1, in1);
            }
            float r2 = fast_sigmoid(grbuf[seq][j & 3][lane] + hsum4(r0, r1_) + b2r);
            float z2 = fast_sigmoid(gzbuf[seq][j & 3][lane] + hsum4(z0, z1_) + b2z);
            float n2 = fast_tanh(hsum4(in0, in1) + bi2n + r2 * (hsum4(n0, n1_) + bh2n));
            h2 = fmaf(z2, h2 - n2, n2);                          // h2(j)
            h2ring[seq][j & 1][lane] = h2;
            __syncwarp();                                        // own cross-lane reads
            NBAR_ARRIVE(emptyb + (j & 1));                       // free slot j
            h2row[(size_t)j * DB + lane] = h2;                   // coalesced STG
        }
    }
}

// ---------------------------------------------------------------------------
// Pass 2: massively parallel output MLP with tail skip.
// ---------------------------------------------------------------------------
__global__ __launch_bounds__(128)
void mlp_kernel(const float* __restrict__ mW1,
                const float* __restrict__ mb1,
                const float* __restrict__ mW2,
                const float* __restrict__ mb2,
                float* __restrict__ out) {
    __shared__ __align__(8) ull   sM1p[DB / 2][DB];   // (mW1[2k][l], mW1[2k+1][l])
    __shared__ __align__(8) float sh[4][32][34];      // per-warp h2 tile, padded
    __shared__ float smb1[DB], smw2[DB];

    const int row = blockIdx.x >> 4;     // 0..511 = kb*256 + b
    const int tg  = blockIdx.x & 15;
    const int kb  = row >> 8;
    const int b   = row & 255;
    const int wid  = threadIdx.x >> 5;
    const int lane = threadIdx.x & 31;

    for (int idx = threadIdx.x; idx < (DB / 2) * DB; idx += blockDim.x) {
        int k = idx >> 5, l = idx & 31;
        sM1p[k][l] = pack2(mW1[kb * DB * DB + (2 * k) * DB + l],
                           mW1[kb * DB * DB + (2 * k + 1) * DB + l]);
    }
    if (threadIdx.x < DB) {
        smb1[threadIdx.x] = mb1[kb * DB + threadIdx.x];
        smw2[threadIdx.x] = mW2[kb * DB + threadIdx.x];
    }
    __syncthreads();

    const int nv   = g_nv[kb][b];
    const int tile = tg * 4 + wid;       // 0..63
    const int t0   = tile * 32;
    const bool boundary = (tile == (nv >> 5));
    if (t0 >= nv && !boundary) return;   // pure-tail tile: filled by boundary warp

    const float* __restrict__ hbase = &g_h2[kb][b][0][0];

    for (int j = 0; j < 32; j++) {
        int t = t0 + j;
        int src = (t < nv) ? t : (nv - 1);
        float v = (nv > 0) ? hbase[(size_t)src * DB + lane] : 0.f;
        sh[wid][j][lane] = v;
    }
    __syncwarp();

    const ull* hrow = (const ull*)&sh[wid][lane][0];
    ull hr[16];
#pragma unroll
    for (int k = 0; k < 16; k++) hr[k] = hrow[k];

    float y = mb2[kb];
#pragma unroll 8
    for (int l = 0; l < DB; l++) {
        ull acc = 0ull;
#pragma unroll
        for (int k = 0; k < 16; k++)
            acc = ffma2(sM1p[k][l], hr[k], acc);
        float hid = fmaxf(hsum2(acc) + smb1[l], 0.f);
        y = fmaf(hid, smw2[l], y);
    }

    float* __restrict__ orow = out + (size_t)row * TT;
    if (!boundary) {
        orow[t0 + lane] = y;
    } else {
        if (t0 + lane < nv) orow[t0 + lane] = y;
        int idx = nv - 1 - t0;
        idx = idx < 0 ? 0 : (idx > 31 ? 31 : idx);
        float y_last = __shfl_sync(FULLMASK, y, idx);
        for (int t = nv + lane; t < TT; t += 32) orow[t] = y_last;
    }
}

// ---------------------------------------------------------------------------
extern "C" void kernel_launch(void* const* d_in, const int* in_sizes, int n_in,
                              void* d_out, int out_size) {
    const int*   band_ids = (const int*)  d_in[0];
    const float* dtime    = (const float*)d_in[1];
    const float* z_last   = (const float*)d_in[2];
    const float* proj_W   = (const float*)d_in[3];
    const float* proj_b   = (const float*)d_in[4];
    const float* Wih      = (const float*)d_in[5];
    const float* Whh      = (const float*)d_in[6];
    const float* bih      = (const float*)d_in[7];
    const float* bhh      = (const float*)d_in[8];
    const float* mW1      = (const float*)d_in[9];
    const float* mb1      = (const float*)d_in[10];
    const float* mW2      = (const float*)d_in[11];
    const float* mb2      = (const float*)d_in[12];
    float* out = (float*)d_out;

    compact_kernel<<<BB / 8, 256>>>(band_ids, dtime);
    rowconst_kernel<<<(LBAND * BB) / 4, 128>>>(z_last, proj_W, proj_b, Wih, bih, bhh);
    gru_main_kernel<<<LBAND * BB / 2, 128>>>(Wih, Whh, bih, bhh);
    mlp_kernel<<<LBAND * BB * 16, 128>>>(mW1, mb1, mW2, mb2, out);
}

// round 17
// speedup vs baseline: 1.0541x; 1.0503x over previous
#include <cuda_runtime.h>

#define FULLMASK 0xffffffffu
typedef unsigned long long ull;

namespace {
constexpr int BB = 256;
constexpr int TT = 2048;
constexpr int DD = 64;
constexpr int LBAND = 2;
constexpr int DB = 32;
constexpr int GG = 96;
constexpr int TPAD = TT + 64;  // dt rows padded so the 32-wide prefetch never reads OOB
}

// Scratch (module-static device globals; no runtime allocation)
__device__ float g_pdt[LBAND][BB][TPAD];
__device__ int   g_nv[LBAND][BB];
__device__ float g_c0[LBAND][BB][GG];
__device__ float g_c1[LBAND][BB][GG];
__device__ float g_h2[LBAND][BB][TT][DB];   // per-step layer-2 hidden states

// Named-barrier producer/consumer primitives (count = 64: 32 arrive + 32 sync)
#define NBAR_SYNC(id)   asm volatile("bar.sync %0, 64;"   :: "r"(id) : "memory")
#define NBAR_ARRIVE(id) asm volatile("bar.arrive %0, 64;" :: "r"(id) : "memory")

// ---------------------------------------------------------------------------
// Kernel 1: stable compaction of valid dtime values per (band,row) + counts
// ---------------------------------------------------------------------------
__global__ void compact_kernel(const int* __restrict__ band_ids,
                               const float* __restrict__ dtime) {
    int warp = threadIdx.x >> 5;
    int lane = threadIdx.x & 31;
    int b = blockIdx.x * (blockDim.x >> 5) + warp;
    if (b >= BB) return;
    int cnt0 = 0, cnt1 = 0;
    int   idc = band_ids[b * TT + lane];
    float dtc = dtime[b * TT + lane];
    for (int base = 0; base < TT; base += 32) {
        int idn = 0; float dtn = 0.f;
        if (base + 32 < TT) {                       // prefetch next tile
            idn = band_ids[b * TT + base + 32 + lane];
            dtn = dtime[b * TT + base + 32 + lane];
        }
        unsigned m0 = __ballot_sync(FULLMASK, idc == 0);
        unsigned lt = (1u << lane) - 1u;
        if (idc == 0) {
            g_pdt[0][b][cnt0 + __popc(m0 & lt)] = dtc;
        } else {
            g_pdt[1][b][cnt1 + __popc((~m0) & lt)] = dtc;
        }
        int p0 = __popc(m0);
        cnt0 += p0;
        cnt1 += 32 - p0;
        idc = idn; dtc = dtn;
    }
    if (lane == 0) { g_nv[0][b] = cnt0; g_nv[1][b] = cnt1; }
}

// ---------------------------------------------------------------------------
// Kernel 2: per-(band,row) affine layer-1 gate constants (bhh folded for r,z)
// ---------------------------------------------------------------------------
__global__ void rowconst_kernel(const float* __restrict__ z_last,
                                const float* __restrict__ proj_W,
                                const float* __restrict__ proj_b,
                                const float* __restrict__ Wih,
                                const float* __restrict__ bih,
                                const float* __restrict__ bhh) {
    int warp = threadIdx.x >> 5;
    int lane = threadIdx.x & 31;
    int wg = blockIdx.x * (blockDim.x >> 5) + warp;
    if (wg >= LBAND * BB) return;
    int kb = wg >> 8;
    int b  = wg & 255;

    float base = proj_b[kb * DB + lane];
#pragma unroll 8
    for (int i = 0; i < DD; i++) {
        base = fmaf(z_last[b * DD + i],
                    proj_W[(kb * (DD + 1) + i) * DB + lane], base);
    }
    float w65 = proj_W[(kb * (DD + 1) + DD) * DB + lane];

    for (int gi = 0; gi < 3; gi++) {
        int g = lane + 32 * gi;
        float c0a = bih[(kb * 2 + 0) * GG + g];
        if (gi < 2) c0a += bhh[(kb * 2 + 0) * GG + g];
        float c1a = 0.f;
        for (int j = 0; j < DB; j++) {
            float bj = __shfl_sync(FULLMASK, base, j);
            float wj = __shfl_sync(FULLMASK, w65, j);
            float w  = Wih[((kb * 2 + 0) * GG + g) * DB + j];
            c0a = fmaf(w, bj, c0a);
            c1a = fmaf(w, wj, c1a);
        }
        g_c0[kb][b][g] = c0a;
        g_c1[kb][b][g] = c1a;
    }
}

// ---------------------------------------------------------------------------
// helpers
// ---------------------------------------------------------------------------
__device__ __forceinline__ ull ffma2(ull a, ull b, ull c) {
    ull d;
    asm("fma.rn.f32x2 %0, %1, %2, %3;" : "=l"(d) : "l"(a), "l"(b), "l"(c));
    return d;
}
__device__ __forceinline__ float hsum2(ull p) {
    float lo, hi;
    asm("mov.b64 {%0, %1}, %2;" : "=f"(lo), "=f"(hi) : "l"(p));
    return lo + hi;
}
__device__ __forceinline__ float hsum4(ull a, ull b) {
    ull s;
    asm("add.rn.f32x2 %0, %1, %2;" : "=l"(s) : "l"(a), "l"(b));
    return hsum2(s);
}
__device__ __forceinline__ ull pack2(float a, float b) {
    ull p;
    asm("mov.b64 %0, {%1, %2};" : "=l"(p) : "f"(a), "f"(b));
    return p;
}
__device__ __forceinline__ float fast_sigmoid(float x) {
    return __fdividef(1.0f, 1.0f + __expf(-x));
}
__device__ __forceinline__ float fast_tanh(float x) {
    return __fdividef(2.0f, 1.0f + __expf(-2.0f * x)) - 1.0f;
}

// ---------------------------------------------------------------------------
// Main GRU kernel: 1 block (4 warps) per TWO sequences, decoupled A/B pairs.
//   wid 0: A(seq0)   wid 1: B(seq0)   wid 2: A(seq1)   wid 3: B(seq1)
// All four SMSPs carry work. Per sequence: warp A runs layer-1 + the r/z
// input gates of layer 2; warp B runs layer-2 and writes h2 to gmem.
// Handoff via 4-deep smem rings + parity-paired named barriers (full:
// base+0/1, empty: base+2/3; count 64; slack 2).
// Best measured configuration (436.0 us, verified twice); FMA-pipe-bound at
// ~87% of the fp32 roofline for this serial recurrence (144 FFMA2 per
// SMSP-step on 2-block SMs). Balancing/skew variants measured neutral-to-worse.
// ---------------------------------------------------------------------------
__global__ __launch_bounds__(128, 1)
void gru_main_kernel(const float* __restrict__ Wih,
                     const float* __restrict__ Whh,
                     const float* __restrict__ bih,
                     const float* __restrict__ bhh) {
    __shared__ __align__(8) float h1ring[2][4][DB];
    __shared__ __align__(8) float grbuf[2][4][DB];
    __shared__ __align__(8) float gzbuf[2][4][DB];
    __shared__ __align__(8) float h2ring[2][2][DB];

    const int wid  = threadIdx.x >> 5;
    const int lane = threadIdx.x & 31;
    const int seq  = wid >> 1;            // 0 or 1
    const int row  = blockIdx.x * 2 + seq;   // kb*256 + b
    const int kb   = row >> 8;
    const int b    = row & 255;
    const int fullb  = 1 + seq * 4;       // full barriers: fullb, fullb+1
    const int emptyb = fullb + 2;         // empty barriers: emptyb, emptyb+1

    const int nv = g_nv[kb][b];
    const float* __restrict__ pdt = &g_pdt[kb][b][0];
    float* __restrict__ h2row = &g_h2[kb][b][0][0];

    if ((wid & 1) == 0) {
        // ===== Warp A: layer 1 + r/z input gates of layer 2 =====
        ull w1r[16], w1z[16], w1n[16], wir[16], wiz[16];
        {
            const ull* pr = (const ull*)(Whh + ((size_t)((kb * 2 + 0) * GG + lane)      * DB));
            const ull* pz = (const ull*)(Whh + ((size_t)((kb * 2 + 0) * GG + lane + 32) * DB));
            const ull* pn = (const ull*)(Whh + ((size_t)((kb * 2 + 0) * GG + lane + 64) * DB));
            const ull* qr = (const ull*)(Wih + ((size_t)((kb * 2 + 1) * GG + lane)      * DB));
            const ull* qz = (const ull*)(Wih + ((size_t)((kb * 2 + 1) * GG + lane + 32) * DB));
#pragma unroll
            for (int k = 0; k < 16; k++) {
                w1r[k] = pr[k]; w1z[k] = pz[k]; w1n[k] = pn[k];
                wir[k] = qr[k]; wiz[k] = qz[k];
            }
        }
        const float c0r = g_c0[kb][b][lane];
        const float c0z = g_c0[kb][b][lane + 32];
        const float c0n = g_c0[kb][b][lane + 64];
        const float c1r = g_c1[kb][b][lane];
        const float c1z = g_c1[kb][b][lane + 32];
        const float c1n = g_c1[kb][b][lane + 64];
        const float bh1n = bhh[(kb * 2 + 0) * GG + lane + 64];

        // prologue: h1(0) from dt(0) with h=0 (recurrent terms vanish except bh1n)
        float dtv = pdt[lane];
        float dt0 = __shfl_sync(FULLMASK, dtv, 0);
        float r1 = fast_sigmoid(fmaf(dt0, c1r, c0r));
        float z1 = fast_sigmoid(fmaf(dt0, c1z, c0z));
        float n1 = fast_tanh(fmaf(dt0, c1n, c0n) + r1 * bh1n);
        float h1 = (1.f - z1) * n1;
        h1ring[seq][0][lane] = h1;
        __syncwarp();

        for (int i = 0; i < nv; i++) {
            if (i >= 2) NBAR_SYNC(emptyb + (i & 1));   // slot freed by B's j = i-2
            if (((i + 1) & 31) == 0) dtv = pdt[i + 1 + lane];   // TPAD: never OOB
            float dtn = __shfl_sync(FULLMASK, dtv, (i + 1) & 31);

            const ull* hp = (const ull*)h1ring[seq][i & 3];     // h1(i), own data
            ull aR0 = 0, aR1 = 0, aZ0 = 0, aZ1 = 0, aN0 = 0, aN1 = 0;
            ull gR0 = 0, gR1 = 0, gZ0 = 0, gZ1 = 0;
#pragma unroll
            for (int k = 0; k < 8; k++) {                       // dual trees, depth 8
                ull p0 = hp[2 * k], p1 = hp[2 * k + 1];
                aR0 = ffma2(w1r[2 * k], p0, aR0); aR1 = ffma2(w1r[2 * k + 1], p1, aR1);
                aZ0 = ffma2(w1z[2 * k], p0, aZ0); aZ1 = ffma2(w1z[2 * k + 1], p1, aZ1);
                aN0 = ffma2(w1n[2 * k], p0, aN0); aN1 = ffma2(w1n[2 * k + 1], p1, aN1);
                gR0 = ffma2(wir[2 * k], p0, gR0); gR1 = ffma2(wir[2 * k + 1], p1, gR1);
                gZ0 = ffma2(wiz[2 * k], p0, gZ0); gZ1 = ffma2(wiz[2 * k + 1], p1, gZ1);
            }
            grbuf[seq][i & 3][lane] = hsum4(gR0, gR1);          // gr(i)
            gzbuf[seq][i & 3][lane] = hsum4(gZ0, gZ1);          // gz(i)

            r1 = fast_sigmoid(fmaf(dtn, c1r, c0r) + hsum4(aR0, aR1));
            z1 = fast_sigmoid(fmaf(dtn, c1z, c0z) + hsum4(aZ0, aZ1));
            n1 = fast_tanh(fmaf(dtn, c1n, c0n) + r1 * (hsum4(aN0, aN1) + bh1n));
            h1 = fmaf(z1, h1 - n1, n1);                         // h1(i+1)
            h1ring[seq][(i + 1) & 3][lane] = h1;
            __syncwarp();                                       // own cross-lane reads
            NBAR_ARRIVE(fullb + (i & 1));                       // publish step i
        }
    } else {
        // ===== Warp B: layer 2 recurrence =====
        ull w2r[16], w2z[16], w2n[16], win[16];
        {
            const ull* pr = (const ull*)(Whh + ((size_t)((kb * 2 + 1) * GG + lane)      * DB));
            const ull* pz = (const ull*)(Whh + ((size_t)((kb * 2 + 1) * GG + lane + 32) * DB));
            const ull* pn = (const ull*)(Whh + ((size_t)((kb * 2 + 1) * GG + lane + 64) * DB));
            const ull* qn = (const ull*)(Wih + ((size_t)((kb * 2 + 1) * GG + lane + 64) * DB));
#pragma unroll
            for (int k = 0; k < 16; k++) {
                w2r[k] = pr[k]; w2z[k] = pz[k]; w2n[k] = pn[k]; win[k] = qn[k];
            }
        }
        const float b2r  = bih[(kb * 2 + 1) * GG + lane]      + bhh[(kb * 2 + 1) * GG + lane];
        const float b2z  = bih[(kb * 2 + 1) * GG + lane + 32] + bhh[(kb * 2 + 1) * GG + lane + 32];
        const float bi2n = bih[(kb * 2 + 1) * GG + lane + 64];
        const float bh2n = bhh[(kb * 2 + 1) * GG + lane + 64];

        h2ring[seq][0][lane] = 0.f;
        h2ring[seq][1][lane] = 0.f;
        float h2 = 0.f;
        __syncwarp();

        for (int j = 0; j < nv; j++) {
            NBAR_SYNC(fullb + (j & 1));             // wait A's publish of step j
            const ull* hpj = (const ull*)h1ring[seq][j & 3];         // h1(j)
            const ull* hp2 = (const ull*)h2ring[seq][(j + 1) & 1];   // h2(j-1)
            ull r0 = 0, r1_ = 0, z0 = 0, z1_ = 0, n0 = 0, n1_ = 0, in0 = 0, in1 = 0;
#pragma unroll
            for (int k = 0; k < 8; k++) {
                ull p0 = hpj[2 * k], p1 = hpj[2 * k + 1];
                ull q0 = hp2[2 * k], q1 = hp2[2 * k + 1];
                r0 = ffma2(w2r[2 * k], q0, r0); r1_ = ffma2(w2r[2 * k + 1], q1, r1_);
                z0 = ffma2(w2z[2 * k], q0, z0); z1_ = ffma2(w2z[2 * k + 1], q1, z1_);
                n0 = ffma2(w2n[2 * k], q0, n0); n1_ = ffma2(w2n[2 * k + 1], q1, n1_);
                in0 = ffma2(win[2 * k], p0, in0); in1 = ffma2(win[2 * k + 1], p1, in1);
            }
            float r2 = fast_sigmoid(grbuf[seq][j & 3][lane] + hsum4(r0, r1_) + b2r);
            float z2 = fast_sigmoid(gzbuf[seq][j & 3][lane] + hsum4(z0, z1_) + b2z);
            float n2 = fast_tanh(hsum4(in0, in1) + bi2n + r2 * (hsum4(n0, n1_) + bh2n));
            h2 = fmaf(z2, h2 - n2, n2);                          // h2(j)
            h2ring[seq][j & 1][lane] = h2;
            __syncwarp();                                        // own cross-lane reads
            NBAR_ARRIVE(emptyb + (j & 1));                       // free slot j
            h2row[(size_t)j * DB + lane] = h2;                   // coalesced STG
        }
    }
}

// ---------------------------------------------------------------------------
// Pass 2: massively parallel output MLP with tail skip.
// ---------------------------------------------------------------------------
__global__ __launch_bounds__(128)
void mlp_kernel(const float* __restrict__ mW1,
                const float* __restrict__ mb1,
                const float* __restrict__ mW2,
                const float* __restrict__ mb2,
                float* __restrict__ out) {
    __shared__ __align__(8) ull   sM1p[DB / 2][DB];   // (mW1[2k][l], mW1[2k+1][l])
    __shared__ __align__(8) float sh[4][32][34];      // per-warp h2 tile, padded
    __shared__ float smb1[DB], smw2[DB];

    const int row = blockIdx.x >> 4;     // 0..511 = kb*256 + b
    const int tg  = blockIdx.x & 15;
    const int kb  = row >> 8;
    const int b   = row & 255;
    const int wid  = threadIdx.x >> 5;
    const int lane = threadIdx.x & 31;

    for (int idx = threadIdx.x; idx < (DB / 2) * DB; idx += blockDim.x) {
        int k = idx >> 5, l = idx & 31;
        sM1p[k][l] = pack2(mW1[kb * DB * DB + (2 * k) * DB + l],
                           mW1[kb * DB * DB + (2 * k + 1) * DB + l]);
    }
    if (threadIdx.x < DB) {
        smb1[threadIdx.x] = mb1[kb * DB + threadIdx.x];
        smw2[threadIdx.x] = mW2[kb * DB + threadIdx.x];
    }
    __syncthreads();

    const int nv   = g_nv[kb][b];
    const int tile = tg * 4 + wid;       // 0..63
    const int t0   = tile * 32;
    const bool boundary = (tile == (nv >> 5));
    if (t0 >= nv && !boundary) return;   // pure-tail tile: filled by boundary warp

    const float* __restrict__ hbase = &g_h2[kb][b][0][0];

    for (int j = 0; j < 32; j++) {
        int t = t0 + j;
        int src = (t < nv) ? t : (nv - 1);
        float v = (nv > 0) ? hbase[(size_t)src * DB + lane] : 0.f;
        sh[wid][j][lane] = v;
    }
    __syncwarp();

    const ull* hrow = (const ull*)&sh[wid][lane][0];
    ull hr[16];
#pragma unroll
    for (int k = 0; k < 16; k++) hr[k] = hrow[k];

    float y = mb2[kb];
#pragma unroll 8
    for (int l = 0; l < DB; l++) {
        ull acc = 0ull;
#pragma unroll
        for (int k = 0; k < 16; k++)
            acc = ffma2(sM1p[k][l], hr[k], acc);
        float hid = fmaxf(hsum2(acc) + smb1[l], 0.f);
        y = fmaf(hid, smw2[l], y);
    }

    float* __restrict__ orow = out + (size_t)row * TT;
    if (!boundary) {
        orow[t0 + lane] = y;
    } else {
        if (t0 + lane < nv) orow[t0 + lane] = y;
        int idx = nv - 1 - t0;
        idx = idx < 0 ? 0 : (idx > 31 ? 31 : idx);
        float y_last = __shfl_sync(FULLMASK, y, idx);
        for (int t = nv + lane; t < TT; t += 32) orow[t] = y_last;
    }
}

// ---------------------------------------------------------------------------
extern "C" void kernel_launch(void* const* d_in, const int* in_sizes, int n_in,
                              void* d_out, int out_size) {
    const int*   band_ids = (const int*)  d_in[0];
    const float* dtime    = (const float*)d_in[1];
    const float* z_last   = (const float*)d_in[2];
    const float* proj_W   = (const float*)d_in[3];
    const float* proj_b   = (const float*)d_in[4];
    const float* Wih      = (const float*)d_in[5];
    const float* Whh      = (const float*)d_in[6];
    const float* bih      = (const float*)d_in[7];
    const float* bhh      = (const float*)d_in[8];
    const float* mW1      = (const float*)d_in[9];
    const float* mb1      = (const float*)d_in[10];
    const float* mW2      = (const float*)d_in[11];
    const float* mb2      = (const float*)d_in[12];
    float* out = (float*)d_out;

    compact_kernel<<<BB / 8, 256>>>(band_ids, dtime);
    rowconst_kernel<<<(LBAND * BB) / 4, 128>>>(z_last, proj_W, proj_b, Wih, bih, bhh);
    gru_main_kernel<<<LBAND * BB / 2, 128>>>(Wih, Whh, bih, bhh);
    mlp_kernel<<<LBAND * BB * 16, 128>>>(mW1, mb1, mW2, mb2, out);
}